// round 6
// baseline (speedup 1.0000x reference)
#include <cuda_runtime.h>
#include <math_constants.h>

// Problem: B=128, L=4096, FILTER_SIZE=2, N_QUBITS=4, 10 classes.
// Analytic reduction: expval_k(b,ol) = K_k * g(b,ol),
//   K_k = cos(p_k1)cos(p_k2)cos(p_k3)   (CNOT ring conjugates Z0 -> Z1Z2Z3)
//   g   = cos(x[ol,1]) * cos(x[ol+1,0]) * cos(x[ol+1,1])
// logits[j] = bias[j] + sum_ol g(ol)*(K0*W[2ol,j]+K1*W[2ol+1,j]); softmax.
#define OLP    4096
#define NCLS   10
#define B_SZ   128
#define NCHUNK 4              // window chunks per row (1024 windows each)
#define RPB    4              // rows per block
#define NT     256
#define W_F4   20475          // float4 count of W (8190*10 floats)
#define SMEM_BYTES (20480 * 4)   // one raw-W chunk: 2048 rows * 10 f = 80KB

// Cross-block combine scratch. Zero at load; every call leaves it zero again.
__device__ float d_logits[B_SZ * NCLS];
__device__ int   d_tick[B_SZ];

__global__ __launch_bounds__(NT, 1)
void qcnn_fused(const float* __restrict__ x,
                const float* __restrict__ params,
                const float* __restrict__ W,
                const float* __restrict__ bias,
                float* __restrict__ out)
{
    extern __shared__ __align__(16) float sw[];   // 20480 floats (80 KB)

    const int c   = blockIdx.x & (NCHUNK - 1);    // window chunk
    const int rg  = blockIdx.x >> 2;              // row group (4 rows)
    const int t   = threadIdx.x;
    const int lane = t & 31;

    // ---- phase A: stage raw W chunk (coalesced), fold into 40 registers ----
    {
        const float4* w4 = (const float4*)W;
        float4* sw4 = (float4*)sw;
        const int base = 5120 * c;
#pragma unroll
        for (int k = 0; k < 20; ++k) {
            int li = t + k * NT;                  // 0..5119
            int gi = base + li;
            sw4[li] = (gi < W_F4) ? w4[gi] : make_float4(0.f, 0.f, 0.f, 0.f);
        }
    }
    __syncthreads();

    const float K0 = __cosf(params[1]) * __cosf(params[2]) * __cosf(params[3]);
    const float K1 = __cosf(params[5]) * __cosf(params[6]) * __cosf(params[7]);

    // wq[j] = folded weight for class j, components = this thread's 4 windows
    float4 wq[NCLS];
    {
        const float4* sw4 = (const float4*)sw;
#pragma unroll
        for (int i = 0; i < 4; ++i) {             // local window 4t+i
            int b0 = 20 * t + 5 * i;
            float4 r0 = sw4[b0];                  // even row f0-3
            float4 r1 = sw4[b0 + 1];              // even f4-7
            float4 r2 = sw4[b0 + 2];              // even f8-9 | odd f0-1
            float4 r3 = sw4[b0 + 3];              // odd f2-5
            float4 r4 = sw4[b0 + 4];              // odd f6-9
            ((float*)&wq[0])[i] = fmaf(K1, r2.z, K0 * r0.x);
            ((float*)&wq[1])[i] = fmaf(K1, r2.w, K0 * r0.y);
            ((float*)&wq[2])[i] = fmaf(K1, r3.x, K0 * r0.z);
            ((float*)&wq[3])[i] = fmaf(K1, r3.y, K0 * r0.w);
            ((float*)&wq[4])[i] = fmaf(K1, r3.z, K0 * r1.x);
            ((float*)&wq[5])[i] = fmaf(K1, r3.w, K0 * r1.y);
            ((float*)&wq[6])[i] = fmaf(K1, r4.x, K0 * r1.z);
            ((float*)&wq[7])[i] = fmaf(K1, r4.y, K0 * r1.w);
            ((float*)&wq[8])[i] = fmaf(K1, r4.z, K0 * r2.x);
            ((float*)&wq[9])[i] = fmaf(K1, r4.w, K0 * r2.y);
        }
    }

    // neighbor-pair gmem offset for lane 31 (clamped for padded window 4095;
    // its weights are 0 so the value is irrelevant, address must be in-range)
    const bool pad = (c == NCHUNK - 1) && (t == NT - 1);
    const int nboff = pad ? 0 : 2 * (1024 * c + 4 * t + 4);

    // ---- phase B: 4 rows, warps fully independent from here on ----
#pragma unroll
    for (int r = 0; r < RPB; ++r) {
        const int row = rg * RPB + r;
        const float* xr = x + (size_t)row * OLP * 2;
        const float4* xr4 = (const float4*)xr;

        float4 v0 = xr4[512 * c + 2 * t];
        float4 v1 = xr4[512 * c + 2 * t + 1];

        float nx = __shfl_down_sync(0xFFFFFFFFu, v0.x, 1);
        float ny = __shfl_down_sync(0xFFFFFFFFu, v0.y, 1);
        if (lane == 31) {
            float2 nb = *(const float2*)(xr + nboff);
            nx = nb.x; ny = nb.y;
        }

        float s1_0 = __cosf(v0.y);
        float s1_1 = __cosf(v0.w), h1 = __cosf(v0.z) * s1_1;
        float s1_2 = __cosf(v1.y), h2 = __cosf(v1.x) * s1_2;
        float s1_3 = __cosf(v1.w), h3 = __cosf(v1.z) * s1_3;
        float h4   = __cosf(nx)   * __cosf(ny);
        float g0 = s1_0 * h1;
        float g1 = s1_1 * h2;
        float g2 = s1_2 * h3;
        float g3 = s1_3 * h4;                     // ×0 weight on the pad window

        float a[NCLS];
#pragma unroll
        for (int j = 0; j < NCLS; ++j) {
            float s = g0 * wq[j].x;
            s = fmaf(g1, wq[j].y, s);
            s = fmaf(g2, wq[j].z, s);
            s = fmaf(g3, wq[j].w, s);
            a[j] = s;
        }

        // warp reduce 10 values
#pragma unroll
        for (int j = 0; j < NCLS; ++j) {
#pragma unroll
            for (int off = 16; off; off >>= 1)
                a[j] += __shfl_xor_sync(0xFFFFFFFFu, a[j], off);
        }

        // combine in gmem; last of the row's 32 warps does the softmax
        int isLast = 0;
        if (lane == 0) {
#pragma unroll
            for (int j = 0; j < NCLS; ++j)
                atomicAdd(&d_logits[row * NCLS + j], a[j]);
            __threadfence();
            isLast = (atomicAdd(&d_tick[row], 1) == NCHUNK * (NT / 32) - 1);
        }
        isLast = __shfl_sync(0xFFFFFFFFu, isLast, 0);
        if (isLast) {
            float logit = -CUDART_INF_F;
            if (lane < NCLS)   // coherent read of the fully combined value
                logit = atomicAdd(&d_logits[row * NCLS + lane], 0.0f) + bias[lane];
            float mx = logit;
#pragma unroll
            for (int off = 16; off; off >>= 1)
                mx = fmaxf(mx, __shfl_xor_sync(0xFFFFFFFFu, mx, off));
            float e = (lane < NCLS) ? __expf(logit - mx) : 0.0f;
            float s = e;
#pragma unroll
            for (int off = 16; off; off >>= 1)
                s += __shfl_xor_sync(0xFFFFFFFFu, s, off);
            if (lane < NCLS) {
                out[row * NCLS + lane] = e / s;
                d_logits[row * NCLS + lane] = 0.0f;   // self-clean for replay
            }
            if (lane == 0) d_tick[row] = 0;
        }
    }
}

// Inputs (metadata order): inputs(128*4096*2 f32), params(8 f32),
//                          W(8190*10 f32), b(10 f32). Output: (128*10) f32.
extern "C" void kernel_launch(void* const* d_in, const int* in_sizes, int n_in,
                              void* d_out, int out_size)
{
    const float* inputs = (const float*)d_in[0];
    const float* params = (const float*)d_in[1];
    const float* W      = (const float*)d_in[2];
    const float* bias   = (const float*)d_in[3];
    float* out          = (float*)d_out;

    static int smem_set = 0;
    if (!smem_set) {
        cudaFuncSetAttribute(qcnn_fused,
                             cudaFuncAttributeMaxDynamicSharedMemorySize,
                             SMEM_BYTES);
        smem_set = 1;
    }
    qcnn_fused<<<B_SZ / RPB * NCHUNK, NT, SMEM_BYTES>>>(inputs, params, W, bias, out);
}

// round 9
// speedup vs baseline: 1.5029x; 1.5029x over previous
#include <cuda_runtime.h>
#include <math_constants.h>
#include <cstdint>

// Problem: B=128, L=4096, FILTER_SIZE=2, N_QUBITS=4, 10 classes.
// Analytic reduction: expval_k(b,ol) = K_k * g(b,ol),
//   K_k = cos(p_k1)cos(p_k2)cos(p_k3)   (CNOT ring conjugates Z0 -> Z1Z2Z3)
//   g   = cos(x[ol,1]) * cos(x[ol+1,0]) * cos(x[ol+1,1])
// logits[j] = bias[j] + sum_ol g(ol)*(K0*W[2ol,j]+K1*W[2ol+1,j]); softmax.
#define OLP    4096
#define NCLS   10
#define B_SZ   128
#define NT     1024
#define HWIN   2048            // windows per block (half row)
#define W_F4   20475           // float4 count of W (8190*10 floats)
#define WP_F4_BLK (NCLS * HWIN / 4)      // 5120 float4 = 80KB smem chunk
#define SMEM_BYTES (WP_F4_BLK * 16)

// Folded, TRANSPOSED weights d_Wp[j*OLP + ol]; column 4095 is zero (pad).
__device__ __align__(16) float d_Wp[NCLS * OLP];
// Cross-block (two halves per row) combine scratch; zero at load, and each
// call leaves it zero again (self-cleaning) so graph replays are correct.
__device__ float d_logits[B_SZ * NCLS];
__device__ int   d_tick[B_SZ];

__device__ __forceinline__ void cp16(unsigned int dst_smem, const void* src)
{
    asm volatile("cp.async.cg.shared.global [%0], [%1], 16;"
                 :: "r"(dst_smem), "l"(src));
}

// ---------------------------------------------------------------------------
// Prep: fold+transpose W into d_Wp. 32 blocks x 256 threads.
// ---------------------------------------------------------------------------
__global__ __launch_bounds__(256) void qcnn_prep(const float* __restrict__ params,
                                                 const float* __restrict__ W)
{
    __shared__ float sw[2560];
    const int bid = blockIdx.x, tid = threadIdx.x;

    const float4* w4 = (const float4*)W;
    const int f4base = bid * 640;
#pragma unroll
    for (int k = 0; k < 3; ++k) {
        int li = tid + k * 256;
        if (li < 640) {
            int gi = f4base + li;
            float4 v = (gi < W_F4) ? w4[gi] : make_float4(0.f, 0.f, 0.f, 0.f);
            *(float4*)&sw[4 * li] = v;
        }
    }
    __syncthreads();

    if (tid < 128) {
        float K0 = __cosf(params[1]) * __cosf(params[2]) * __cosf(params[3]);
        float K1 = __cosf(params[5]) * __cosf(params[6]) * __cosf(params[7]);
        int ol = bid * 128 + tid;
        const float* r = &sw[20 * tid];          // rows 2ol, 2ol+1 (10 floats each)
#pragma unroll
        for (int j = 0; j < NCLS; ++j)
            d_Wp[j * OLP + ol] = fmaf(K1, r[10 + j], K0 * r[j]);
    }
}

// ---------------------------------------------------------------------------
// Main: 128 blocks = 64 row-pairs x 2 window-halves; 1024 threads.
// Warps 0-15 -> row 2rg, warps 16-31 -> row 2rg+1; both rows share the SAME
// smem Wp chunk (cp.async-staged), halving the L2 weight broadcast.
// Thread tp of half h owns windows 2048h+4tp .. +3  (x float4 idx 1024h+2tp).
// ---------------------------------------------------------------------------
__global__ __launch_bounds__(NT, 1) void qcnn_main(const float* __restrict__ x,
                                                   const float* __restrict__ bias,
                                                   float* __restrict__ out)
{
    extern __shared__ __align__(16) float4 sWp[];   // [NCLS][HWIN/4] = 5120 f4
    __shared__ float sred[32][NCLS];

    const int rg   = blockIdx.x >> 1;        // row pair index
    const int h    = blockIdx.x & 1;         // window half
    const int tid  = threadIdx.x;
    const int lane = tid & 31;
    const int tp   = tid & 511;              // thread-in-half, 0..511
    const int row  = rg * 2 + (tid >> 9);    // warps 0-15: row A, 16-31: row B

    // ---- phase 0: stage the 80KB Wp chunk via cp.async (overlaps phase 1)
    {
        unsigned int sbase;
        asm("{ .reg .u64 a; cvta.to.shared.u64 a, %1; cvt.u32.u64 %0, a; }"
            : "=r"(sbase) : "l"(sWp));
        const float4* src = (const float4*)d_Wp;
#pragma unroll
        for (int k = 0; k < 5; ++k) {
            int li = tid + k * NT;                          // 0..5119
            int j = li >> 9, col = li & 511;                // class, col-of-4
            cp16(sbase + 16u * li, src + j * (OLP / 4) + h * 512 + col);
        }
        asm volatile("cp.async.commit_group;");
    }

    // ---- phase 1: x loads + cos (independent of the smem staging)
    const float* xr = x + (size_t)row * OLP * 2;
    const float4* xr4 = (const float4*)xr;
    float4 v0 = xr4[1024 * h + 2 * tp];          // pairs 2048h+4tp, +1
    float4 v1 = xr4[1024 * h + 2 * tp + 1];      // pairs 2048h+4tp+2, +3

    float nx = __shfl_down_sync(0xFFFFFFFFu, v0.x, 1);
    float ny = __shfl_down_sync(0xFFFFFFFFu, v0.y, 1);
    if (lane == 31) {
        int wend = HWIN * h + 4 * tp + 4;                   // next pair index
        int off = (wend >= OLP) ? 0 : 2 * wend;             // clamp pad (w=0 there)
        float2 nb = *(const float2*)(xr + off);
        nx = nb.x; ny = nb.y;
    }

    float s1_0 = __cosf(v0.y);
    float s1_1 = __cosf(v0.w), h1 = __cosf(v0.z) * s1_1;
    float s1_2 = __cosf(v1.y), h2 = __cosf(v1.x) * s1_2;
    float s1_3 = __cosf(v1.w), h3 = __cosf(v1.z) * s1_3;
    float h4   = __cosf(nx)   * __cosf(ny);
    float g0 = s1_0 * h1;
    float g1 = s1_1 * h2;
    float g2 = s1_2 * h3;
    float g3 = s1_3 * h4;             // padded window 4095 has zero weight

    // ---- phase 2: smem dot (conflict-free LDS.128, lane stride 16B)
    asm volatile("cp.async.wait_group 0;");
    __syncthreads();

    float acc[NCLS];
#pragma unroll
    for (int j = 0; j < NCLS; ++j) {
        float4 w = sWp[j * 512 + tp];
        float a;
        a = g0 * w.x;
        a = fmaf(g1, w.y, a);
        a = fmaf(g2, w.z, a);
        a = fmaf(g3, w.w, a);
        acc[j] = a;
    }

    // ---- phase 3: per-row reduce (16 warps each)
#pragma unroll
    for (int j = 0; j < NCLS; ++j) {
#pragma unroll
        for (int off = 16; off; off >>= 1)
            acc[j] += __shfl_xor_sync(0xFFFFFFFFu, acc[j], off);
    }
    const int warp = tid >> 5;
    if (lane == 0) {
#pragma unroll
        for (int j = 0; j < NCLS; ++j) sred[warp][j] = acc[j];
    }
    __syncthreads();

    // ---- phase 4: half-row partial -> gmem combine; last half does softmax.
    // Warp 0 finishes row A, warp 16 finishes row B (run concurrently).
    if ((tid & 511) < 32) {
        const int wbase = (tid >> 9) * 16;
        float part = 0.0f;
        if (lane < NCLS) {
#pragma unroll
            for (int w = 0; w < 16; ++w) part += sred[wbase + w][lane];
            atomicAdd(&d_logits[row * NCLS + lane], part);
        }
        __threadfence();
        int isLast = 0;
        if (lane == 0) isLast = (atomicAdd(&d_tick[row], 1) == 1);
        isLast = __shfl_sync(0xFFFFFFFFu, isLast, 0);
        if (isLast) {
            float logit = -CUDART_INF_F;
            if (lane < NCLS)     // atomic read => L2-coherent combined value
                logit = atomicAdd(&d_logits[row * NCLS + lane], 0.0f) + bias[lane];
            float mx = logit;
#pragma unroll
            for (int off = 16; off; off >>= 1)
                mx = fmaxf(mx, __shfl_xor_sync(0xFFFFFFFFu, mx, off));
            float e = (lane < NCLS) ? __expf(logit - mx) : 0.0f;
            float s = e;
#pragma unroll
            for (int off = 16; off; off >>= 1)
                s += __shfl_xor_sync(0xFFFFFFFFu, s, off);
            if (lane < NCLS) {
                out[row * NCLS + lane] = e / s;
                d_logits[row * NCLS + lane] = 0.0f;   // self-clean for replay
            }
            if (lane == 0) d_tick[row] = 0;
        }
    }
}

// Inputs (metadata order): inputs(128*4096*2 f32), params(8 f32),
//                          W(8190*10 f32), b(10 f32). Output: (128*10) f32.
extern "C" void kernel_launch(void* const* d_in, const int* in_sizes, int n_in,
                              void* d_out, int out_size)
{
    const float* inputs = (const float*)d_in[0];
    const float* params = (const float*)d_in[1];
    const float* W      = (const float*)d_in[2];
    const float* bias   = (const float*)d_in[3];
    float* out          = (float*)d_out;

    static int smem_set = 0;
    if (!smem_set) {
        cudaFuncSetAttribute(qcnn_main,
                             cudaFuncAttributeMaxDynamicSharedMemorySize,
                             SMEM_BYTES);
        smem_set = 1;
    }
    qcnn_prep<<<32, 256>>>(params, W);
    qcnn_main<<<B_SZ, NT, SMEM_BYTES>>>(inputs, bias, out);
}

// round 10
// speedup vs baseline: 1.5162x; 1.0088x over previous
#include <cuda_runtime.h>
#include <math_constants.h>
#include <cstdint>

// Problem: B=128, L=4096, FILTER_SIZE=2, N_QUBITS=4, 10 classes.
// Analytic reduction: expval_k(b,ol) = K_k * g(b,ol),
//   K_k = cos(p_k1)cos(p_k2)cos(p_k3)   (CNOT ring conjugates Z0 -> Z1Z2Z3)
//   g   = cos(x[ol,1]) * cos(x[ol+1,0]) * cos(x[ol+1,1])
// logits[j] = bias[j] + sum_ol g(ol)*(K0*W[2ol,j]+K1*W[2ol+1,j]); softmax.
#define OLP    4096
#define NCLS   10
#define B_SZ   128
#define NT     1024
#define W_F4   20475          // float4 count of W (8190*10 floats)

// Folded, TRANSPOSED weights d_Wp[j*OLP + ol]; column 4095 ends up zero (pad).
__device__ __align__(16) float d_Wp[NCLS * OLP];
// Grid-barrier + reset tickets (zero at load; kernel leaves them zero again).
__device__ int d_done;
__device__ int d_fin;

// ---------------------------------------------------------------------------
// Single fused kernel: 128 blocks x 1024 threads, one batch row per block.
// Block b also folds Wp columns [32b, 32b+32) before a device-wide barrier.
// All 128 blocks are co-resident (<=148 SMs, 1 block/SM) => spin is safe.
// ---------------------------------------------------------------------------
__global__ __launch_bounds__(NT, 1) void qcnn_one(const float* __restrict__ x,
                                                  const float* __restrict__ params,
                                                  const float* __restrict__ W,
                                                  const float* __restrict__ bias,
                                                  float* __restrict__ out)
{
    __shared__ __align__(16) float sw[640];     // 160 float4 of raw W
    __shared__ float sred[32][NCLS];

    const int b    = blockIdx.x;
    const int tid  = threadIdx.x;
    const int lane = tid & 31;

    // ---- issue x loads first: DRAM latency drains behind the fold/barrier
    const float* xr = x + (size_t)b * OLP * 2;
    const float4* xr4 = (const float4*)xr;
    float4 v0 = xr4[2 * tid];                   // pairs 4t, 4t+1
    float4 v1 = xr4[2 * tid + 1];               // pairs 4t+2, 4t+3

    // ---- fold this block's Wp slice: columns [32b, 32b+32)
    if (tid < 160) {                            // W float4 [160b, 160b+160)
        int gi = 160 * b + tid;
        float4 v = (gi < W_F4) ? ((const float4*)W)[gi]
                               : make_float4(0.f, 0.f, 0.f, 0.f);
        *(float4*)&sw[4 * tid] = v;
    }
    __syncthreads();
    if (tid < 32) {
        float K0 = __cosf(params[1]) * __cosf(params[2]) * __cosf(params[3]);
        float K1 = __cosf(params[5]) * __cosf(params[6]) * __cosf(params[7]);
        int ol = 32 * b + tid;
        const float* r = &sw[20 * tid];         // rows 2ol (10 f), 2ol+1 (10 f)
#pragma unroll
        for (int j = 0; j < NCLS; ++j)
            d_Wp[j * OLP + ol] = fmaf(K1, r[10 + j], K0 * r[j]);
        __threadfence();                        // publish this thread's stores
    }
    __syncthreads();
    if (tid == 0) atomicAdd(&d_done, 1);        // arrive at grid barrier

    // ---- cos work overlaps other blocks' folds and the barrier wait
    float nx = __shfl_down_sync(0xFFFFFFFFu, v0.x, 1);
    float ny = __shfl_down_sync(0xFFFFFFFFu, v0.y, 1);
    if (lane == 31) {
        int off = (tid == NT - 1) ? 0 : 8 * tid + 8;   // clamp pad (weight=0)
        float2 nb = *(const float2*)(xr + off);
        nx = nb.x; ny = nb.y;
    }
    float s1_0 = __cosf(v0.y);
    float s1_1 = __cosf(v0.w), h1 = __cosf(v0.z) * s1_1;
    float s1_2 = __cosf(v1.y), h2 = __cosf(v1.x) * s1_2;
    float s1_3 = __cosf(v1.w), h3 = __cosf(v1.z) * s1_3;
    float h4   = __cosf(nx)   * __cosf(ny);
    float g0 = s1_0 * h1;
    float g1 = s1_1 * h2;
    float g2 = s1_2 * h3;
    float g3 = s1_3 * h4;                       // padded window: folded w = 0

    // ---- wait for all 128 fold slices
    if (tid == 0) {
        while (atomicAdd(&d_done, 0) < B_SZ) __nanosleep(32);
    }
    __syncthreads();

    // ---- dot with folded weights: 10 coalesced, L2-hot LDG.128 (R4-proven)
    const float4* Wp4 = (const float4*)d_Wp;
    float acc[NCLS];
#pragma unroll
    for (int j = 0; j < NCLS; ++j) {
        float4 w = Wp4[j * (OLP / 4) + tid];
        float a;
        a = g0 * w.x;
        a = fmaf(g1, w.y, a);
        a = fmaf(g2, w.z, a);
        a = fmaf(g3, w.w, a);
        acc[j] = a;
    }

    // ---- reduce 1024 threads -> 10 logits
#pragma unroll
    for (int j = 0; j < NCLS; ++j) {
#pragma unroll
        for (int off = 16; off; off >>= 1)
            acc[j] += __shfl_xor_sync(0xFFFFFFFFu, acc[j], off);
    }
    const int warp = tid >> 5;
    if (lane == 0) {
#pragma unroll
        for (int j = 0; j < NCLS; ++j) sred[warp][j] = acc[j];
    }
    __syncthreads();

    // ---- final reduce + softmax in warp 0 (lanes 0..9 own one class)
    if (tid < 32) {
        float logit = -CUDART_INF_F;
        if (tid < NCLS) {
            logit = bias[tid];
#pragma unroll
            for (int w = 0; w < 32; ++w) logit += sred[w][tid];
        }
        float mx = logit;
#pragma unroll
        for (int off = 16; off; off >>= 1)
            mx = fmaxf(mx, __shfl_xor_sync(0xFFFFFFFFu, mx, off));
        float e = (tid < NCLS) ? __expf(logit - mx) : 0.0f;
        float s = e;
#pragma unroll
        for (int off = 16; off; off >>= 1)
            s += __shfl_xor_sync(0xFFFFFFFFu, s, off);
        if (tid < NCLS) out[b * NCLS + tid] = e / s;
    }

    // ---- last block to finish resets the barrier counters (replay-safe)
    if (tid == 0) {
        int f = atomicAdd(&d_fin, 1);
        if (f == B_SZ - 1) { d_done = 0; d_fin = 0; __threadfence(); }
    }
}

// Inputs (metadata order): inputs(128*4096*2 f32), params(8 f32),
//                          W(8190*10 f32), b(10 f32). Output: (128*10) f32.
extern "C" void kernel_launch(void* const* d_in, const int* in_sizes, int n_in,
                              void* d_out, int out_size)
{
    const float* inputs = (const float*)d_in[0];
    const float* params = (const float*)d_in[1];
    const float* W      = (const float*)d_in[2];
    const float* bias   = (const float*)d_in[3];
    float* out          = (float*)d_out;

    qcnn_one<<<B_SZ, NT>>>(inputs, params, W, bias, out);
}